// round 15
// baseline (speedup 1.0000x reference)
#include <cuda_runtime.h>

#define BSZ    512
#define NN     128
#define NMAT   2560
#define SS     132           // partial-buffer stride: 132 ≡ 4 (mod 32)
#define TS     36            // warp subtile row stride: 36 ≡ 4 (mod 32)
#define LOG2E  1.4426950408889634f

__device__ __forceinline__ float frcp(float x) {
    float r;
    asm("rcp.approx.ftz.f32 %0, %1;" : "=f"(r) : "f"(x));
    return r;
}
__device__ __forceinline__ float fex2(float x) {
    float r;
    asm("ex2.approx.ftz.f32 %0, %1;" : "=f"(r) : "f"(x));
    return r;
}

// ---------------- persistent scratch (__device__ globals) -------------------
__device__ float g_Ts[128];          // sorted ReLU thresholds
__device__ float g_A [129 * 128];    // per-interval slope * log2e
__device__ float g_Cc[129 * 128];    // per-interval offset * log2e (incl b2)

// ---------------- kernel 1: fused prep (rank + tables + Ts) -----------------
__global__ void k_prep(const float* __restrict__ w1, const float* __restrict__ b1,
                       const float* __restrict__ w2, const float* __restrict__ b2)
{
    __shared__ float tsh[128], wss[128], bss[128];
    __shared__ int   ps[128];
    extern __shared__ float w2t[];    // [128][129] transposed w2

    const int j = threadIdx.x;        // output column 0..127
    const int k = blockIdx.x;         // interval 0..128

    float w  = w1[j];
    float bb = b1[j];
    float tv = (w != 0.0f) ? (-bb / w) : (bb > 0.0f ? -3.0e38f : 3.0e38f);
    tsh[j] = tv;
    __syncthreads();
    int r = 0;
    #pragma unroll 8
    for (int p = 0; p < 128; ++p) {
        float o = tsh[p];
        r += (o < tv) || (o == tv && p < j);
    }
    wss[r] = w;
    bss[r] = bb;
    ps[r]  = j;
    if (k == 0) g_Ts[r] = tv;

    #pragma unroll 4
    for (int t = 0; t < 128; ++t)
        w2t[j * 129 + t] = w2[t * 128 + j];
    __syncthreads();

    float a = 0.f, c = 0.f;
    #pragma unroll 4
    for (int p = 0; p < 128; ++p) {
        float wv = wss[p], bv = bss[p];
        bool pos = (wv > 0.f) || (wv == 0.f && bv > 0.f);
        bool act = pos ? (p < k) : (p >= k);
        if (act) {
            float mm = w2t[ps[p] * 129 + j];
            a = fmaf(wv, mm, a);
            c = fmaf(bv, mm, c);
        }
    }
    g_A [k * 128 + j] = a * LOG2E;                     // premultiplied log2e
    g_Cc[k * 128 + j] = (c + b2[j]) * LOG2E;
}

// ---------------- kernel 2: dual-register-slice Sinkhorn --------------------
// warp w: g=w>>2 (rows 32g..), q=w&3 (cols 32q..); lane -> row r=32g+lane.
// Thread holds BOTH its row slice rr[8] (M0[r][32q..+31]) AND its column
// slice cc[8] (M0[32g..+31][32q+lane]) in registers -> the loop touches smem
// only for broadcast vector reads + one partial STS per phase.
// 2 CTA barriers/iter; reduces are warp-redundant into private WR/WC copies.
__global__ __launch_bounds__(512) void k_sinkhorn(
    const float* __restrict__ x,
    const float* __restrict__ noise,
    float* __restrict__ out)
{
    extern __shared__ float sm[];
    float* sub = sm;                      // [16][32*TS] per-warp subtiles
    float* P1  = sm + 16 * 32 * TS;       // [4][SS] row partials (by quarter)
    float* P2  = P1 + 4 * SS;             // [4][SS] col partials (by group)
    float* WR  = P2 + 4 * SS;             // [16][32] per-warp R copies
    float* WC  = WR + 16 * 32;            // [16][32] per-warp C copies

    const int m    = blockIdx.x;
    const int b    = m & (BSZ - 1);
    const int tid  = threadIdx.x;
    const int lane = tid & 31;
    const int wrp  = tid >> 5;
    const int g    = wrp >> 2;
    const int q    = wrp & 3;
    const int r    = 32 * g + lane;

    // ---- own x and interval index (L1/L2-hot __ldg binary search) ----------
    const float xv_own = __ldg(x + b * NN + r);
    int lo = 0, hi = 128;
    #pragma unroll
    for (int s = 0; s < 7; ++s) {
        int mid = (lo + hi) >> 1;
        if (__ldg(g_Ts + mid) < xv_own) lo = mid + 1; else hi = mid;
    }
    const int kr_own = lo;

    // ---- warp-local prologue: 32x32 subtile, 4 rows per step ---------------
    float* mysub = sub + wrp * (32 * TS);
    const float* nz = noise + (size_t)m * (NN * NN) + (32 * g) * NN + 32 * q;
    const int oct = lane >> 3;             // 0..3 row-within-step
    const int c8  = 4 * (lane & 7);        // 0,4,..,28 column quad
    #pragma unroll
    for (int t = 0; t < 8; ++t) {
        int   src = 4 * t + oct;
        float xr  = __shfl_sync(0xffffffffu, xv_own, src);
        int   kt  = __shfl_sync(0xffffffffu, kr_own, src);
        float4 a4 = *(const float4*)(g_A  + kt * 128 + 32 * q + c8);
        float4 q4 = *(const float4*)(g_Cc + kt * 128 + 32 * q + c8);
        float4 n4 = *(const float4*)(nz + src * NN + c8);
        float4 e;
        e.x = fex2(fmaf(n4.x, LOG2E, fmaf(a4.x, xr, q4.x)));
        e.y = fex2(fmaf(n4.y, LOG2E, fmaf(a4.y, xr, q4.y)));
        e.z = fex2(fmaf(n4.z, LOG2E, fmaf(a4.z, xr, q4.z)));
        e.w = fex2(fmaf(n4.w, LOG2E, fmaf(a4.w, xr, q4.w)));
        *(float4*)(mysub + src * TS + c8) = e;              // CF (stride 36)
    }
    __syncwarp();

    // ---- pickup BOTH slices into registers ---------------------------------
    float4 rr[8];                          // row slice: M0[r][32q+0..31]
    #pragma unroll
    for (int p = 0; p < 8; ++p)
        rr[p] = *(const float4*)(mysub + lane * TS + 4 * p);   // CF vec4
    float4 cc[8];                          // col slice: M0[32g+j][32q+lane]
    #pragma unroll
    for (int p = 0; p < 8; ++p) {          // CF scalar LDS (banks 4(4p+e)+lane)
        cc[p].x = mysub[(4 * p + 0) * TS + lane];
        cc[p].y = mysub[(4 * p + 1) * TS + lane];
        cc[p].z = mysub[(4 * p + 2) * TS + lane];
        cc[p].w = mysub[(4 * p + 3) * TS + lane];
    }

    const float* myWR = WR + wrp * 32;
    const float* myWC = WC + wrp * 32;
    float Rl = 0.f;

    #pragma unroll 1
    for (int it = 0; it < 10; ++it) {
        // (1) row dot: sum(rr * C)  (iteration 0: C == 1, plain sum)
        float4 acc;
        if (it == 0) {
            acc = make_float4(rr[0].x + rr[4].x, rr[0].y + rr[4].y,
                              rr[0].z + rr[4].z, rr[0].w + rr[4].w);
            acc.x += rr[1].x + rr[5].x; acc.y += rr[1].y + rr[5].y;
            acc.z += rr[1].z + rr[5].z; acc.w += rr[1].w + rr[5].w;
            acc.x += rr[2].x + rr[6].x; acc.y += rr[2].y + rr[6].y;
            acc.z += rr[2].z + rr[6].z; acc.w += rr[2].w + rr[6].w;
            acc.x += rr[3].x + rr[7].x; acc.y += rr[3].y + rr[7].y;
            acc.z += rr[3].z + rr[7].z; acc.w += rr[3].w + rr[7].w;
        } else {
            acc = make_float4(0.f, 0.f, 0.f, 0.f);
            #pragma unroll
            for (int p = 0; p < 8; ++p) {
                float4 c4 = *(const float4*)(myWC + 4 * p);    // bcast, 1 wf
                acc.x = fmaf(rr[p].x, c4.x, acc.x);
                acc.y = fmaf(rr[p].y, c4.y, acc.y);
                acc.z = fmaf(rr[p].z, c4.z, acc.z);
                acc.w = fmaf(rr[p].w, c4.w, acc.w);
            }
        }
        P1[q * SS + r] = (acc.x + acc.y) + (acc.z + acc.w);    // CF STS
        __syncthreads();

        // (2) warp-redundant R reduce: R for own row -> private copy
        Rl = frcp((P1[0 * SS + r] + P1[1 * SS + r]) +
                  (P1[2 * SS + r] + P1[3 * SS + r]));          // CF LDS x4
        WR[wrp * 32 + lane] = Rl;
        __syncwarp();

        // (3) col dot: sum(cc * R[32g..])  from private R copy
        float4 tac = make_float4(0.f, 0.f, 0.f, 0.f);
        #pragma unroll
        for (int p = 0; p < 8; ++p) {
            float4 rv = *(const float4*)(myWR + 4 * p);        // bcast, 1 wf
            tac.x = fmaf(cc[p].x, rv.x, tac.x);
            tac.y = fmaf(cc[p].y, rv.y, tac.y);
            tac.z = fmaf(cc[p].z, rv.z, tac.z);
            tac.w = fmaf(cc[p].w, rv.w, tac.w);
        }
        P2[g * SS + 32 * q + lane] = (tac.x + tac.y) + (tac.z + tac.w);
        __syncthreads();

        // (4) warp-redundant C reduce: C for own column -> private copy
        {
            int ci = 32 * q + lane;
            float cs = frcp((P2[0 * SS + ci] + P2[1 * SS + ci]) +
                            (P2[2 * SS + ci] + P2[3 * SS + ci]));
            WC[wrp * 32 + lane] = cs;
        }
        __syncwarp();
    }

    // ---- epilogue: out[m][c][r] = M0[r][c]*R_r*C_c, DIRECT from registers --
    {
        float* om = out + (size_t)m * (NN * NN) + (32 * q) * NN + 32 * g + lane;
        #pragma unroll
        for (int p = 0; p < 8; ++p) {
            float4 c4 = *(const float4*)(myWC + 4 * p);        // bcast
            float sx = rr[p].x * Rl, sy = rr[p].y * Rl;
            float sz = rr[p].z * Rl, sw = rr[p].w * Rl;
            om[(4 * p + 0) * NN] = sx * c4.x;   // coalesced 128B STG.32
            om[(4 * p + 1) * NN] = sy * c4.y;
            om[(4 * p + 2) * NN] = sz * c4.z;
            om[(4 * p + 3) * NN] = sw * c4.w;
        }
    }
}

// ---------------- launch ----------------------------------------------------
extern "C" void kernel_launch(void* const* d_in, const int* in_sizes, int n_in,
                              void* d_out, int out_size)
{
    const float* x     = (const float*)d_in[0];
    const float* w1    = (const float*)d_in[1];
    const float* b1    = (const float*)d_in[2];
    const float* w2    = (const float*)d_in[3];
    const float* b2    = (const float*)d_in[4];
    const float* noise = (const float*)d_in[5];
    float* out = (float*)d_out;

    const int prep_smem = 128 * 129 * 4;                    // 66,048 B
    cudaFuncSetAttribute(k_prep, cudaFuncAttributeMaxDynamicSharedMemorySize,
                         prep_smem);
    k_prep<<<129, 128, prep_smem>>>(w1, b1, w2, b2);

    // sub + P1 + P2 + WR + WC
    const int smem_words = 16 * 32 * TS + 2 * 4 * SS + 2 * 16 * 32;
    const int smem_bytes = smem_words * 4;                  // 82,048 B
    cudaFuncSetAttribute(k_sinkhorn, cudaFuncAttributeMaxDynamicSharedMemorySize,
                         smem_bytes);
    k_sinkhorn<<<NMAT, 512, smem_bytes>>>(x, noise, out);
}

// round 16
// speedup vs baseline: 1.0316x; 1.0316x over previous
#include <cuda_runtime.h>

#define BSZ    512
#define NN     128
#define NMAT   2560
#define SS     132           // partial stride (words): 132 ≡ 4 (mod 32)
#define TS     36            // warp subtile row stride: 36 ≡ 4 (mod 32)
#define LOG2E  1.4426950408889634f

__device__ __forceinline__ float frcp(float x) {
    float r;
    asm("rcp.approx.ftz.f32 %0, %1;" : "=f"(r) : "f"(x));
    return r;
}
__device__ __forceinline__ float fex2(float x) {
    float r;
    asm("ex2.approx.ftz.f32 %0, %1;" : "=f"(r) : "f"(x));
    return r;
}

// ---------------- persistent scratch (__device__ globals) -------------------
__device__ float g_Ts[128];          // sorted ReLU thresholds
__device__ float g_A [129 * 128];    // per-interval slope * log2e
__device__ float g_Cc[129 * 128];    // per-interval offset * log2e (incl b2)

// ---------------- kernel 1: fused prep (rank + tables + Ts) -----------------
__global__ void k_prep(const float* __restrict__ w1, const float* __restrict__ b1,
                       const float* __restrict__ w2, const float* __restrict__ b2)
{
    __shared__ float tsh[128], wss[128], bss[128];
    __shared__ int   ps[128];
    extern __shared__ float w2t[];    // [128][129] transposed w2

    const int j = threadIdx.x;        // output column 0..127
    const int k = blockIdx.x;         // interval 0..128

    float w  = w1[j];
    float bb = b1[j];
    float tv = (w != 0.0f) ? (-bb / w) : (bb > 0.0f ? -3.0e38f : 3.0e38f);
    tsh[j] = tv;
    __syncthreads();
    int r = 0;
    #pragma unroll 8
    for (int p = 0; p < 128; ++p) {
        float o = tsh[p];
        r += (o < tv) || (o == tv && p < j);
    }
    wss[r] = w;
    bss[r] = bb;
    ps[r]  = j;
    if (k == 0) g_Ts[r] = tv;

    #pragma unroll 4
    for (int t = 0; t < 128; ++t)
        w2t[j * 129 + t] = w2[t * 128 + j];
    __syncthreads();

    float a = 0.f, c = 0.f;
    #pragma unroll 4
    for (int p = 0; p < 128; ++p) {
        float wv = wss[p], bv = bss[p];
        bool pos = (wv > 0.f) || (wv == 0.f && bv > 0.f);
        bool act = pos ? (p < k) : (p >= k);
        if (act) {
            float mm = w2t[ps[p] * 129 + j];
            a = fmaf(wv, mm, a);
            c = fmaf(bv, mm, c);
        }
    }
    g_A [k * 128 + j] = a * LOG2E;
    g_Cc[k * 128 + j] = (c + b2[j]) * LOG2E;
}

// ---------------- kernel 2: register-resident Sinkhorn, 2 barriers/iter -----
// warp w: g=w>>2 (rows 32g..), q=w&3 (cols 32q..); lane -> row r=32g+lane.
// Loop: [row dot -> P1] bar [warp-redundant R + butterfly -> P2] bar
//       [warp-redundant C -> WC, syncwarp] ...  No idle phases, no dbl-buffer.
__global__ __launch_bounds__(512, 2) void k_sinkhorn(
    const float* __restrict__ x,
    const float* __restrict__ noise,
    float* __restrict__ out)
{
    extern __shared__ float sm[];
    float* sub = sm;                      // [16][32*TS] per-warp subtiles
    float* P1  = sm + 16 * 32 * TS;       // [4][SS] row partials (by quarter)
    float* P2  = P1 + 4 * SS;             // [4][SS] col partials (by group)
    float* WC  = P2 + 4 * SS;             // [16][32] per-warp C copies

    const int m    = blockIdx.x;
    const int b    = m & (BSZ - 1);
    const int tid  = threadIdx.x;
    const int lane = tid & 31;
    const int wrp  = tid >> 5;
    const int g    = wrp >> 2;
    const int q    = wrp & 3;
    const int r    = 32 * g + lane;

    // ---- own x and interval index (L1/L2-hot __ldg binary search) ----------
    const float xv_own = __ldg(x + b * NN + r);
    int lo = 0, hi = 128;
    #pragma unroll
    for (int s = 0; s < 7; ++s) {
        int mid = (lo + hi) >> 1;
        if (__ldg(g_Ts + mid) < xv_own) lo = mid + 1; else hi = mid;
    }
    const int kr_own = lo;

    // ---- warp-local prologue: 32x32 subtile, 4 rows per step ---------------
    float* mysub = sub + wrp * (32 * TS);
    const float* nz = noise + (size_t)m * (NN * NN) + (32 * g) * NN + 32 * q;
    const int oct = lane >> 3;
    const int c8  = 4 * (lane & 7);
    #pragma unroll
    for (int t = 0; t < 8; ++t) {
        int   src = 4 * t + oct;
        float xr  = __shfl_sync(0xffffffffu, xv_own, src);
        int   kt  = __shfl_sync(0xffffffffu, kr_own, src);
        float4 a4 = *(const float4*)(g_A  + kt * 128 + 32 * q + c8);
        float4 q4 = *(const float4*)(g_Cc + kt * 128 + 32 * q + c8);
        float4 n4 = *(const float4*)(nz + src * NN + c8);
        float4 e;
        e.x = fex2(fmaf(n4.x, LOG2E, fmaf(a4.x, xr, q4.x)));
        e.y = fex2(fmaf(n4.y, LOG2E, fmaf(a4.y, xr, q4.y)));
        e.z = fex2(fmaf(n4.z, LOG2E, fmaf(a4.z, xr, q4.z)));
        e.w = fex2(fmaf(n4.w, LOG2E, fmaf(a4.w, xr, q4.w)));
        *(float4*)(mysub + src * TS + c8) = e;              // CF (stride 36)
    }
    __syncwarp();

    // ---- pickup own row slice (CF vec4, stride 36) -------------------------
    float4 rr[8];
    #pragma unroll
    for (int p = 0; p < 8; ++p)
        rr[p] = *(const float4*)(mysub + lane * TS + 4 * p);
    const float* af = (const float*)rr;

    const float* myWC = WC + wrp * 32;
    float Rl = 0.f;

    #pragma unroll 1
    for (int it = 0; it < 10; ++it) {
        // ---- (1) row dot: sum(rr * C)  (it 0: C == 1, plain sum) -----------
        float4 acc;
        if (it == 0) {
            acc = make_float4(rr[0].x + rr[4].x, rr[0].y + rr[4].y,
                              rr[0].z + rr[4].z, rr[0].w + rr[4].w);
            acc.x += rr[1].x + rr[5].x; acc.y += rr[1].y + rr[5].y;
            acc.z += rr[1].z + rr[5].z; acc.w += rr[1].w + rr[5].w;
            acc.x += rr[2].x + rr[6].x; acc.y += rr[2].y + rr[6].y;
            acc.z += rr[2].z + rr[6].z; acc.w += rr[2].w + rr[6].w;
            acc.x += rr[3].x + rr[7].x; acc.y += rr[3].y + rr[7].y;
            acc.z += rr[3].z + rr[7].z; acc.w += rr[3].w + rr[7].w;
        } else {
            acc = make_float4(0.f, 0.f, 0.f, 0.f);
            #pragma unroll
            for (int p = 0; p < 8; ++p) {
                float4 c4 = *(const float4*)(myWC + 4 * p);    // bcast
                acc.x = fmaf(rr[p].x, c4.x, acc.x);
                acc.y = fmaf(rr[p].y, c4.y, acc.y);
                acc.z = fmaf(rr[p].z, c4.z, acc.z);
                acc.w = fmaf(rr[p].w, c4.w, acc.w);
            }
        }
        P1[q * SS + r] = (acc.x + acc.y) + (acc.z + acc.w);    // CF STS
        __syncthreads();                                       // barrier 1

        // ---- (2) warp-redundant R for own row (CF: banks 4e+lane) ----------
        Rl = frcp((P1[0 * SS + r] + P1[1 * SS + r]) +
                  (P1[2 * SS + r] + P1[3 * SS + r]));

        // ---- (3) butterfly col dot over warp rows, R folded into stage 1 ---
        #pragma unroll
        for (int pass = 0; pass < 2; ++pass) {
            const int cb = 16 * pass;
            float w8[8];
            {
                bool up = (lane & 16) != 0;
                #pragma unroll
                for (int j = 0; j < 8; ++j) {
                    float a_lo = af[cb + j];
                    float a_hi = af[cb + j + 8];
                    float send = (up ? a_lo : a_hi) * Rl;
                    float keep = (up ? a_hi : a_lo);
                    float recv = __shfl_xor_sync(0xffffffffu, send, 16);
                    w8[j] = fmaf(keep, Rl, recv);
                }
            }
            #pragma unroll
            for (int off = 8; off >= 2; off >>= 1) {
                int n = off >> 1;
                bool up = (lane & off) != 0;
                #pragma unroll
                for (int j = 0; j < n; ++j) {
                    float send = up ? w8[j] : w8[j + n];
                    float keep = up ? w8[j + n] : w8[j];
                    float recv = __shfl_xor_sync(0xffffffffu, send, off);
                    w8[j] = keep + recv;
                }
            }
            float v = w8[0] + __shfl_xor_sync(0xffffffffu, w8[0], 1);
            if ((lane & 1) == 0)
                P2[g * SS + 32 * q + cb + ((lane >> 1) & 15)] = v;
        }
        __syncthreads();                                       // barrier 2

        // ---- (4) warp-redundant C for own column (CF: banks 4g+lane) -------
        {
            int ci = 32 * q + lane;
            float cs = frcp((P2[0 * SS + ci] + P2[1 * SS + ci]) +
                            (P2[2 * SS + ci] + P2[3 * SS + ci]));
            WC[wrp * 32 + lane] = cs;
        }
        __syncwarp();
    }

    // ---- epilogue: out[m][c][r] = M0[r][c]*R_r*C_c, DIRECT from registers --
    {
        float* om = out + (size_t)m * (NN * NN) + (32 * q) * NN + 32 * g + lane;
        #pragma unroll
        for (int p = 0; p < 8; ++p) {
            float4 c4 = *(const float4*)(myWC + 4 * p);        // bcast
            float sx = rr[p].x * Rl, sy = rr[p].y * Rl;
            float sz = rr[p].z * Rl, sw = rr[p].w * Rl;
            om[(4 * p + 0) * NN] = sx * c4.x;   // coalesced 128B STG.32
            om[(4 * p + 1) * NN] = sy * c4.y;
            om[(4 * p + 2) * NN] = sz * c4.z;
            om[(4 * p + 3) * NN] = sw * c4.w;
        }
    }
}

// ---------------- launch ----------------------------------------------------
extern "C" void kernel_launch(void* const* d_in, const int* in_sizes, int n_in,
                              void* d_out, int out_size)
{
    const float* x     = (const float*)d_in[0];
    const float* w1    = (const float*)d_in[1];
    const float* b1    = (const float*)d_in[2];
    const float* w2    = (const float*)d_in[3];
    const float* b2    = (const float*)d_in[4];
    const float* noise = (const float*)d_in[5];
    float* out = (float*)d_out;

    const int prep_smem = 128 * 129 * 4;                    // 66,048 B
    cudaFuncSetAttribute(k_prep, cudaFuncAttributeMaxDynamicSharedMemorySize,
                         prep_smem);
    k_prep<<<129, 128, prep_smem>>>(w1, b1, w2, b2);

    // sub + P1 + P2 + WC
    const int smem_words = 16 * 32 * TS + 2 * 4 * SS + 16 * 32;
    const int smem_bytes = smem_words * 4;                  // 80,000 B
    cudaFuncSetAttribute(k_sinkhorn, cudaFuncAttributeMaxDynamicSharedMemorySize,
                         smem_bytes);
    k_sinkhorn<<<NMAT, 512, smem_bytes>>>(x, noise, out);
}